// round 14
// baseline (speedup 1.0000x reference)
#include <cuda_runtime.h>
#include <math.h>

// ---------------------------------------------------------------------------
// MTCNN P-net pyramid, B=4, 1080x1080x3, 12 scales.  R13 = R12 +
//  - resize_v: per-row tap-window predicates -> bit-exact vs reference
//  - conv3head: TX=4 px/thread, 16-of-32 oc per thread (lane pairs),
//    double-buffered input, head partials combined via one shfl_xor.
// Stages: resize_h(all scales) | resize_v | conv1+pool | conv2 | conv3+heads
// ---------------------------------------------------------------------------

#define BATCH 4
#define HIN 1080
#define NS 12

typedef unsigned long long u64;

__device__ __forceinline__ u64 pack2(float x) {
    u64 r; asm("mov.b64 %0, {%1, %1};" : "=l"(r) : "f"(x)); return r;
}
__device__ __forceinline__ u64 pk2(float lo, float hi) {
    u64 r; asm("mov.b64 %0, {%1, %2};" : "=l"(r) : "f"(lo), "f"(hi)); return r;
}
__device__ __forceinline__ void unpk(u64 v, float& lo, float& hi) {
    asm("mov.b64 {%0, %1}, %2;" : "=f"(lo), "=f"(hi) : "l"(v));
}
__device__ __forceinline__ void ffma2(u64& d, u64 a, u64 b) {
    asm("fma.rn.f32x2 %0, %1, %2, %3;" : "=l"(d) : "l"(a), "l"(b), "l"(d));
}
__device__ __forceinline__ u64 addx2(u64 a, u64 b) {
    u64 r; asm("add.rn.f32x2 %0, %1, %2;" : "=l"(r) : "l"(a), "l"(b)); return r;
}
__device__ __forceinline__ float lrelu(float z) { return z > 0.f ? z : 0.3f * z; }

__device__ float g_tmpH[28460160 + 1024];  // [4,1080,ws,3] interleaved
__device__ float g_img [10145112 + 1024];  // [4,3,hs,ws]  planar
__device__ float g_p1  [ 8377240 + 1024];  // [4,10,h2,w2] planar
__device__ float g_c2  [13127872 + 1024];  // [4,16,h3,w3] planar

struct Meta {
    int   hs[NS];
    float inv[NS], rinv[NS], scl[NS];
    int   offT[NS], offI[NS], offP[NS], offC[NS];
    int   offW[NS];
    int   wsum;
    int   noff[NS];
    int   ntot;
    int   bsRV[NS + 1], bsCP[NS + 1], bsC2[NS + 1], bsC3[NS + 1];
};

__device__ __forceinline__ int fscale(const int* bs)
{
    int k = 0;
#pragma unroll
    for (int i = 1; i < NS; i++)
        if ((int)blockIdx.x >= bs[i]) k = i;
    return k;
}

// ---------------------------------------------------------------------------
// Stage 1: horizontal antialiased resize, ALL scales fused.
// ---------------------------------------------------------------------------
__global__ void __launch_bounds__(256)
k_resize_h(const float* __restrict__ in, Meta m)
{
    __shared__ float srow[HIN * 3];
    int by = blockIdx.x;
    const float* rp = in + by * (HIN * 3);
    for (int i = threadIdx.x; i < HIN * 3; i += 256) srow[i] = rp[i];
    __syncthreads();

    for (int it = threadIdx.x; it < m.wsum; it += 256) {
        int k = 0;
#pragma unroll
        for (int i = 1; i < NS; i++)
            if (it >= m.offW[i]) k = i;
        int ox = it - m.offW[k];
        int ws = m.hs[k];
        float inv = m.inv[k], rinv = m.rinv[k];

        float sf = (ox + 0.5f) * inv - 0.5f;
        int j0 = (int)ceilf(sf - inv);  if (j0 < 0) j0 = 0;
        int j1 = (int)floorf(sf + inv); if (j1 > HIN - 1) j1 = HIN - 1;
        float a0 = 0.f, a1 = 0.f, a2 = 0.f, wsum = 0.f;
        const float* s = srow + j0 * 3;
        float fj = (float)j0;
        for (int j = j0; j <= j1; j++) {
            float wv = fmaxf(fmaf(fabsf(sf - fj), -rinv, 1.f), 0.f);
            wsum += wv;
            a0 = fmaf(wv, s[0], a0);
            a1 = fmaf(wv, s[1], a1);
            a2 = fmaf(wv, s[2], a2);
            s += 3; fj += 1.f;
        }
        float sc = 1.f / wsum;
        float* o = g_tmpH + m.offT[k] + (by * ws + ox) * 3;
        o[0] = a0 * sc; o[1] = a1 * sc; o[2] = a2 * sc;
    }
}

// ---------------------------------------------------------------------------
// Stage 2: vertical resize + (x-127.5)/128 -> planar img.
// 2 consecutive output rows per thread; shared taps, per-row exact windows.
// ---------------------------------------------------------------------------
__global__ void k_resize_v(Meta m)
{
    int k = fscale(m.bsRV);
    int hs = m.hs[k], ws = hs;
    int ph = (hs + 1) >> 1;
    float inv = m.inv[k], rinv = m.rinv[k];
    int idx = (blockIdx.x - m.bsRV[k]) * blockDim.x + threadIdx.x;
    if (idx >= BATCH * ph * ws) return;
    int x  = idx % ws;
    int t  = idx / ws;
    int p  = t % ph;
    int b  = t / ph;
    int oy0 = 2 * p;
    bool has1 = (oy0 + 1) < hs;

    float sf0 = (oy0 + 0.5f) * inv - 0.5f;
    float sf1 = (oy0 + 1.5f) * inv - 0.5f;
    float sfL = has1 ? sf1 : sf0;
    int j0 = (int)ceilf(sf0 - inv);  if (j0 < 0) j0 = 0;
    int j1 = (int)floorf(sfL + inv); if (j1 > HIN - 1) j1 = HIN - 1;
    // exact per-row windows (match reference tap sets bit-for-bit)
    int j1r0 = (int)floorf(sf0 + inv); if (j1r0 > HIN - 1) j1r0 = HIN - 1;
    int j0r1 = (int)ceilf(sf1 - inv);  if (j0r1 < 0) j0r1 = 0;

    float a00 = 0.f, a01 = 0.f, a02 = 0.f, ws0 = 0.f;
    float a10 = 0.f, a11 = 0.f, a12 = 0.f, ws1 = 0.f;
    const float* ptap = g_tmpH + m.offT[k] + ((b * HIN + j0) * ws + x) * 3;
    int step = ws * 3;
    float fj = (float)j0;
    for (int j = j0; j <= j1; j++) {
        float w0 = fmaxf(fmaf(fabsf(sf0 - fj), -rinv, 1.f), 0.f);
        float w1 = fmaxf(fmaf(fabsf(sf1 - fj), -rinv, 1.f), 0.f);
        if (j > j1r0) w0 = 0.f;
        if (j < j0r1) w1 = 0.f;
        float v0 = ptap[0], v1 = ptap[1], v2 = ptap[2];
        ws0 += w0; ws1 += w1;
        a00 = fmaf(w0, v0, a00);
        a01 = fmaf(w0, v1, a01);
        a02 = fmaf(w0, v2, a02);
        a10 = fmaf(w1, v0, a10);
        a11 = fmaf(w1, v1, a11);
        a12 = fmaf(w1, v2, a12);
        ptap += step; fj += 1.f;
    }

    int plane = hs * ws;
    float* ob = g_img + m.offI[k] + b * 3 * plane + oy0 * ws + x;
    {
        float s = 1.f / ws0;
        ob[0]         = (a00 * s - 127.5f) * (1.f / 128.f);
        ob[plane]     = (a01 * s - 127.5f) * (1.f / 128.f);
        ob[2 * plane] = (a02 * s - 127.5f) * (1.f / 128.f);
    }
    if (has1) {
        float s = 1.f / ws1;
        ob += ws;
        ob[0]         = (a10 * s - 127.5f) * (1.f / 128.f);
        ob[plane]     = (a11 * s - 127.5f) * (1.f / 128.f);
        ob[2 * plane] = (a12 * s - 127.5f) * (1.f / 128.f);
    }
}

// ---------------------------------------------------------------------------
// Stage 3: conv3x3 3->10 + lrelu fused with 2x2/2 maxpool. Planar in/out.
// ---------------------------------------------------------------------------
__global__ void __launch_bounds__(128, 4)
k_conv1pool(const float* __restrict__ w, const float* __restrict__ bias, Meta m)
{
    __shared__ __align__(16) float ws_[27 * 12];
    __shared__ __align__(8)  float bs_[10];
    for (int i = threadIdx.x; i < 270; i += blockDim.x) {
        int e = i / 10, p = i - e * 10;
        ws_[e * 12 + p] = w[i];
    }
    if (threadIdx.x < 10) bs_[threadIdx.x] = bias[threadIdx.x];
    __syncthreads();

    int k = fscale(m.bsCP);
    int hs = m.hs[k], ws = hs;
    int h1 = hs - 2, w1 = ws - 2;
    int h2 = (h1 + 1) >> 1, w2 = (w1 + 1) >> 1;
    int idx = (blockIdx.x - m.bsCP[k]) * blockDim.x + threadIdx.x;
    if (idx >= BATCH * h2 * w2) return;
    int x = idx % w2;
    int t = idx / w2;
    int y = t % h2;
    int b = t / h2;
    int r0 = 2 * y, c0 = 2 * x;
    bool vr = (r0 + 1 < h1), vc = (c0 + 1 < w1);

    u64 acc[4][5];
    {
        const u64* bq = (const u64*)bs_;
#pragma unroll
        for (int p = 0; p < 4; p++) {
            u64 b0 = bq[0], b1 = bq[1], b2 = bq[2], b3 = bq[3], b4 = bq[4];
            acc[p][0] = b0; acc[p][1] = b1; acc[p][2] = b2; acc[p][3] = b3; acc[p][4] = b4;
        }
    }

    int plane = hs * ws;
    const float* imgb = g_img + m.offI[k] + b * 3 * plane;

#pragma unroll
    for (int ic = 0; ic < 3; ic++) {
        u64 pp[4][4];
#pragma unroll
        for (int i = 0; i < 4; i++) {
            int ry = r0 + i; if (ry > hs - 1) ry = hs - 1;
            const float* rp = imgb + ic * plane + ry * ws;
#pragma unroll
            for (int j = 0; j < 4; j++) {
                int cx = c0 + j; if (cx > ws - 1) cx = ws - 1;
                pp[i][j] = pack2(__ldg(rp + cx));
            }
        }
#pragma unroll
        for (int ky = 0; ky < 3; ky++)
#pragma unroll
        for (int kx = 0; kx < 3; kx++) {
            const float* wbase = ws_ + ((ky * 3 + kx) * 3 + ic) * 12;
            ulonglong2 w01 = *(const ulonglong2*)wbase;
            ulonglong2 w23 = *(const ulonglong2*)(wbase + 4);
            u64        w4  = *(const u64*)(wbase + 8);
            u64 wv[5] = { w01.x, w01.y, w23.x, w23.y, w4 };
#pragma unroll
            for (int q = 0; q < 5; q++) {
                ffma2(acc[0][q], pp[ky][kx],         wv[q]);
                ffma2(acc[1][q], pp[ky][kx + 1],     wv[q]);
                ffma2(acc[2][q], pp[ky + 1][kx],     wv[q]);
                ffma2(acc[3][q], pp[ky + 1][kx + 1], wv[q]);
            }
        }
    }

    int oplane = h2 * w2;
    float* ob = g_p1 + m.offP[k] + b * 10 * oplane + y * w2 + x;
#pragma unroll
    for (int q = 0; q < 5; q++) {
        float z0, z1, a0, a1, u0, u1;
        unpk(acc[0][q], z0, z1); a0 = lrelu(z0); a1 = lrelu(z1);
        if (vc) { unpk(acc[1][q], z0, z1); a0 = fmaxf(a0, lrelu(z0)); a1 = fmaxf(a1, lrelu(z1)); }
        if (vr) { unpk(acc[2][q], z0, z1); a0 = fmaxf(a0, lrelu(z0)); a1 = fmaxf(a1, lrelu(z1));
            if (vc) { unpk(acc[3][q], u0, u1); a0 = fmaxf(a0, lrelu(u0)); a1 = fmaxf(a1, lrelu(u1)); } }
        ob[(2 * q)     * oplane] = a0;
        ob[(2 * q + 1) * oplane] = a1;
    }
}

// ---------------------------------------------------------------------------
// Stage 4: conv3x3 10->16 + lrelu. TX=4 (R9 shape). Double-buffered input.
// ---------------------------------------------------------------------------
__global__ void __launch_bounds__(128, 4)
k_conv2(const float* __restrict__ w, const float* __restrict__ bias, Meta m)
{
    __shared__ __align__(16) float ws_[1440];
    __shared__ __align__(8)  float bs_[16];
    {
        const float4* s4 = (const float4*)w;
        float4* d4 = (float4*)ws_;
        for (int i = threadIdx.x; i < 360; i += blockDim.x) d4[i] = s4[i];
        if (threadIdx.x < 16) bs_[threadIdx.x] = bias[threadIdx.x];
    }
    __syncthreads();

    int k = fscale(m.bsC2);
    int hs = m.hs[k];
    int hin = (hs - 1) >> 1, win = hin;
    int hout = hin - 2, wout = win - 2;
    int WG = (wout + 3) >> 2;
    int idx = (blockIdx.x - m.bsC2[k]) * blockDim.x + threadIdx.x;
    if (idx >= BATCH * hout * WG) return;
    int xg = idx % WG;
    int t2 = idx / WG;
    int y  = t2 % hout;
    int b  = t2 / hout;
    int x0 = xg * 4;

    u64 acc[4][8];
    {
        const u64* bq = (const u64*)bs_;
#pragma unroll
        for (int q = 0; q < 8; q++) {
            u64 bv = bq[q];
            acc[0][q] = bv; acc[1][q] = bv; acc[2][q] = bv; acc[3][q] = bv;
        }
    }

    int plane = hin * win;
    const float* pb = g_p1 + m.offP[k] + b * 10 * plane;
    int xc[6];
#pragma unroll
    for (int t = 0; t < 6; t++) { int xx = x0 + t; xc[t] = xx > win - 1 ? win - 1 : xx; }

#pragma unroll
    for (int ky = 0; ky < 3; ky++) {
        const float* rbase = pb + (y + ky) * win;
        u64 vbuf[2][6];
#pragma unroll
        for (int t = 0; t < 6; t++) vbuf[0][t] = pack2(__ldg(rbase + xc[t]));

#pragma unroll 2
        for (int ic = 0; ic < 10; ic++) {
            int cur = ic & 1;
            if (ic < 9) {
                const float* rn = rbase + (ic + 1) * plane;
#pragma unroll
                for (int t = 0; t < 6; t++) vbuf[cur ^ 1][t] = pack2(__ldg(rn + xc[t]));
            }
#pragma unroll
            for (int kx = 0; kx < 3; kx++) {
                const ulonglong2* wq = (const ulonglong2*)(ws_ + ((ky * 3 + kx) * 10 + ic) * 16);
#pragma unroll
                for (int q2 = 0; q2 < 4; q2++) {
                    ulonglong2 wv = wq[q2];
#pragma unroll
                    for (int t = 0; t < 4; t++) {
                        ffma2(acc[t][2 * q2 + 0], vbuf[cur][t + kx], wv.x);
                        ffma2(acc[t][2 * q2 + 1], vbuf[cur][t + kx], wv.y);
                    }
                }
            }
        }
    }

    int oplane = hout * wout;
    float* ob = g_c2 + m.offC[k] + b * 16 * oplane + y * wout;
#pragma unroll
    for (int t = 0; t < 4; t++) {
        int x = x0 + t;
        if (x < wout) {
#pragma unroll
            for (int q = 0; q < 8; q++) {
                float z0, z1;
                unpk(acc[t][q], z0, z1);
                ob[(2 * q)     * oplane + x] = lrelu(z0);
                ob[(2 * q + 1) * oplane + x] = lrelu(z1);
            }
        }
    }
}

// ---------------------------------------------------------------------------
// Stage 5: conv3x3 16->32 + lrelu + heads + boxes + mask.
// TX=4 px/thread, 16-of-32 oc per thread (even lane: oc 0-15, odd: 16-31).
// Double-buffered input (addresses duplicated in lane pairs -> same sectors).
// Heads combined across the pair via one shfl_xor + add.rn.f32x2.
// Output layout: boxes[4][N][5] | reg[4][N][4] | mask[4][N]
// ---------------------------------------------------------------------------
__global__ void __launch_bounds__(128, 4)
k_conv3head(const float* __restrict__ w, const float* __restrict__ bias,
            const float* __restrict__ wp, const float* __restrict__ bp,
            const float* __restrict__ wr, const float* __restrict__ br,
            float* __restrict__ out, Meta m)
{
    __shared__ __align__(16) float ws_[4608];
    __shared__ __align__(8)  float cb_[32], hwp[64], hwr[128], hb[6];
    {
        const float4* s4 = (const float4*)w;
        float4* d4 = (float4*)ws_;
        for (int i = threadIdx.x; i < 1152; i += blockDim.x) d4[i] = s4[i];
        if (threadIdx.x < 32) cb_[threadIdx.x] = bias[threadIdx.x];
        if (threadIdx.x < 64) hwp[threadIdx.x] = wp[threadIdx.x];
        hwr[threadIdx.x] = wr[threadIdx.x];
        if (threadIdx.x == 64) { hb[0] = bp[0]; hb[1] = bp[1]; }
        if (threadIdx.x == 65) { hb[2] = br[0]; hb[3] = br[1]; hb[4] = br[2]; hb[5] = br[3]; }
    }
    __syncthreads();

    int k = fscale(m.bsC3);
    int hs = m.hs[k];
    int hin = ((hs - 1) >> 1) - 2, win = hin;
    int hout = hin - 2, wout = win - 2;
    int WG = (wout + 3) >> 2;
    int ngroups = BATCH * hout * WG;
    int idx = (blockIdx.x - m.bsC3[k]) * blockDim.x + threadIdx.x;
    int half = idx & 1;
    int gid = idx >> 1;
    bool alive = gid < ngroups;
    if (!alive) gid = ngroups - 1;          // keep lanes running for shfl
    int xg = gid % WG;
    int t2 = gid / WG;
    int y  = t2 % hout;
    int b  = t2 / hout;
    int x0 = xg * 4;

    u64 acc[4][8];
    {
        const u64* bq = (const u64*)cb_;     // 16 u64 = 32 floats
#pragma unroll
        for (int q = 0; q < 8; q++) {
            u64 bv = bq[half * 8 + q];
            acc[0][q] = bv; acc[1][q] = bv; acc[2][q] = bv; acc[3][q] = bv;
        }
    }

    int plane = hin * win;
    const float* cbase = g_c2 + m.offC[k] + b * 16 * plane;
    int xc[6];
#pragma unroll
    for (int t = 0; t < 6; t++) { int xx = x0 + t; xc[t] = xx > win - 1 ? win - 1 : xx; }

#pragma unroll
    for (int ky = 0; ky < 3; ky++) {
        const float* rbase = cbase + (y + ky) * win;
        u64 vbuf[2][6];
#pragma unroll
        for (int t = 0; t < 6; t++) vbuf[0][t] = pack2(__ldg(rbase + xc[t]));

#pragma unroll 2
        for (int ic = 0; ic < 16; ic++) {
            int cur = ic & 1;
            if (ic < 15) {
                const float* rn = rbase + (ic + 1) * plane;
#pragma unroll
                for (int t = 0; t < 6; t++) vbuf[cur ^ 1][t] = pack2(__ldg(rn + xc[t]));
            }
#pragma unroll
            for (int kx = 0; kx < 3; kx++) {
                const ulonglong2* wq =
                    (const ulonglong2*)(ws_ + ((ky * 3 + kx) * 16 + ic) * 32 + half * 16);
                ulonglong2 wA = wq[0], wB = wq[1], wC = wq[2], wD = wq[3];
#pragma unroll
                for (int t = 0; t < 4; t++) {
                    u64 v = vbuf[cur][t + kx];
                    ffma2(acc[t][0], v, wA.x);
                    ffma2(acc[t][1], v, wA.y);
                    ffma2(acc[t][2], v, wB.x);
                    ffma2(acc[t][3], v, wB.y);
                    ffma2(acc[t][4], v, wC.x);
                    ffma2(acc[t][5], v, wC.y);
                    ffma2(acc[t][6], v, wD.x);
                    ffma2(acc[t][7], v, wD.y);
                }
            }
        }
    }

    int ntot = m.ntot;
    float scale = m.scl[k];
    int nbase = m.noff[k] + y * wout;
    float fy = (float)y;
    const u64* wp64 = (const u64*)hwp;
    const u64* wr64 = (const u64*)hwr;
    u64 zero = pk2(0.f, 0.f);

#pragma unroll
    for (int t = 0; t < 4; t++) {
        u64 zz = (half == 0) ? pk2(hb[0], hb[1]) : zero;
        u64 rA = (half == 0) ? pk2(hb[2], hb[3]) : zero;
        u64 rB = (half == 0) ? pk2(hb[4], hb[5]) : zero;
#pragma unroll
        for (int q = 0; q < 8; q++) {
            float z0, z1;
            unpk(acc[t][q], z0, z1);
            u64 v0 = pack2(lrelu(z0));
            u64 v1 = pack2(lrelu(z1));
            int c0 = half * 16 + 2 * q, c1 = c0 + 1;
            ffma2(zz, v0, wp64[c0]);         ffma2(zz, v1, wp64[c1]);
            ffma2(rA, v0, wr64[2 * c0]);     ffma2(rA, v1, wr64[2 * c1]);
            ffma2(rB, v0, wr64[2 * c0 + 1]); ffma2(rB, v1, wr64[2 * c1 + 1]);
        }
        // combine oc halves across the lane pair
        zz = addx2(zz, __shfl_xor_sync(0xffffffffu, zz, 1));
        rA = addx2(rA, __shfl_xor_sync(0xffffffffu, rA, 1));
        rB = addx2(rB, __shfl_xor_sync(0xffffffffu, rB, 1));

        int x = x0 + t;
        if (alive && half == 0 && x < wout) {
            float z0, z1, r0, r1, r2, r3;
            unpk(zz, z0, z1);
            unpk(rA, r0, r1);
            unpk(rB, r2, r3);
            float score = 1.f / (1.f + expf(z0 - z1));

            int n = nbase + x;
            float fx = (float)x;
            float ulr = rintf((fy * 2.f + 1.f)  / scale);
            float ulc = rintf((fx * 2.f + 1.f)  / scale);
            float drr = rintf((fy * 2.f + 12.f) / scale);
            float drc = rintf((fx * 2.f + 12.f) / scale);

            float* pbx = out + (b * ntot + n) * 5;
            pbx[0] = ulr; pbx[1] = ulc; pbx[2] = drr; pbx[3] = drc; pbx[4] = score;

            float* prg = out + BATCH * ntot * 5 + (b * ntot + n) * 4;
            prg[0] = r0; prg[1] = r1; prg[2] = r2; prg[3] = r3;

            out[BATCH * ntot * 9 + b * ntot + n] = (score >= 0.6f) ? 1.f : 0.f;
        }
    }
}

// ---------------------------------------------------------------------------
extern "C" void kernel_launch(void* const* d_in, const int* in_sizes, int n_in,
                              void* d_out, int out_size)
{
    const float* inp = (const float*)d_in[0];
    const float* w1  = (const float*)d_in[1];
    const float* b1  = (const float*)d_in[2];
    const float* w2  = (const float*)d_in[3];
    const float* b2  = (const float*)d_in[4];
    const float* w3  = (const float*)d_in[5];
    const float* b3  = (const float*)d_in[6];
    const float* wp  = (const float*)d_in[7];
    const float* bp  = (const float*)d_in[8];
    const float* wr  = (const float*)d_in[9];
    const float* br  = (const float*)d_in[10];
    float* out = (float*)d_out;
    (void)in_sizes; (void)n_in; (void)out_size;

    Meta m;
    int ns = 0;
    {
        double s = 12.0 / 20.0, mm = s * 1080.0;
        while (mm >= 12.0 && ns < NS) {
            m.hs[ns]   = (int)ceil(1080.0 * s);
            m.inv[ns]  = (float)(1080.0 / (double)m.hs[ns]);
            m.rinv[ns] = (float)((double)m.hs[ns] / 1080.0);
            m.scl[ns]  = (float)s;
            ns++;
            s *= 0.709; mm *= 0.709;
        }
    }

    int oT = 0, oI = 0, oP = 0, oC = 0, oW = 0, ntot = 0;
    m.bsRV[0] = m.bsCP[0] = m.bsC2[0] = m.bsC3[0] = 0;
    for (int k = 0; k < ns; k++) {
        int hs = m.hs[k], ws = hs;
        int h1 = hs - 2;
        int h2 = (h1 + 1) / 2, w2d = h2;
        int h3 = h2 - 2, w3d = h3;
        int h4 = h3 - 2, w4 = h4;
        int ph = (hs + 1) / 2;

        m.offT[k] = oT;  oT += BATCH * HIN * ws * 3;
        m.offI[k] = oI;  oI += BATCH * hs * ws * 3;
        m.offP[k] = oP;  oP += BATCH * h2 * w2d * 10;
        m.offC[k] = oC;  oC += BATCH * h3 * w3d * 16;
        m.offW[k] = oW;  oW += ws;
        m.noff[k] = ntot; ntot += h4 * w4;

        int T;
        T = BATCH * ph * ws;                   m.bsRV[k+1] = m.bsRV[k] + (T + 255) / 256;
        T = BATCH * h2 * w2d;                  m.bsCP[k+1] = m.bsCP[k] + (T + 127) / 128;
        T = BATCH * h3 * ((w2d - 2 + 3) / 4);  m.bsC2[k+1] = m.bsC2[k] + (T + 127) / 128;
        T = 2 * BATCH * h4 * ((w4 + 3) / 4);   m.bsC3[k+1] = m.bsC3[k] + (T + 127) / 128;
    }
    m.ntot = ntot;
    m.wsum = oW;
    for (int k = ns; k < NS; k++) {
        m.hs[k] = m.hs[ns-1]; m.inv[k] = m.inv[ns-1];
        m.rinv[k] = m.rinv[ns-1]; m.scl[k] = m.scl[ns-1];
        m.offT[k] = m.offI[k] = m.offP[k] = m.offC[k] = 0; m.noff[k] = 0;
        m.bsRV[k+1] = m.bsRV[k];
        m.bsCP[k+1] = m.bsCP[k]; m.bsC2[k+1] = m.bsC2[k]; m.bsC3[k+1] = m.bsC3[k];
        m.offW[k] = 0x7fffffff;
        m.bsRV[k] = 0x7fffffff; m.bsCP[k] = 0x7fffffff;
        m.bsC2[k] = 0x7fffffff; m.bsC3[k] = 0x7fffffff;
    }

    k_resize_h <<<BATCH * HIN, 256>>>(inp, m);
    k_resize_v <<<m.bsRV[ns], 256>>>(m);
    k_conv1pool<<<m.bsCP[ns], 128>>>(w1, b1, m);
    k_conv2    <<<m.bsC2[ns], 128>>>(w2, b2, m);
    k_conv3head<<<m.bsC3[ns], 128>>>(w3, b3, wp, bp, wr, br, out, m);
}

// round 15
// speedup vs baseline: 1.0624x; 1.0624x over previous
#include <cuda_runtime.h>
#include <math.h>

// ---------------------------------------------------------------------------
// MTCNN P-net pyramid, B=4, 1080x1080x3, 12 scales.  R14:
//  - g_p1 / g_c2 rows padded to 4-float-aligned strides (+slack) so conv
//    inputs load as LDG.128/LDG.64 instead of scalar LDG.32 (L1-line work /3)
//  - conv2: float4+float2 input loads, no clamp math
//  - conv3head: R9 shape (TX=2, full 32 oc) with 2x float2 loads
//  - resize_v: exact per-row tap windows (R13)
// Stages: resize_h(all scales) | resize_v | conv1+pool | conv2 | conv3+heads
// ---------------------------------------------------------------------------

#define BATCH 4
#define HIN 1080
#define NS 12

typedef unsigned long long u64;

__device__ __forceinline__ u64 pack2(float x) {
    u64 r; asm("mov.b64 %0, {%1, %1};" : "=l"(r) : "f"(x)); return r;
}
__device__ __forceinline__ u64 pk2(float lo, float hi) {
    u64 r; asm("mov.b64 %0, {%1, %2};" : "=l"(r) : "f"(lo), "f"(hi)); return r;
}
__device__ __forceinline__ void unpk(u64 v, float& lo, float& hi) {
    asm("mov.b64 {%0, %1}, %2;" : "=f"(lo), "=f"(hi) : "l"(v));
}
__device__ __forceinline__ void ffma2(u64& d, u64 a, u64 b) {
    asm("fma.rn.f32x2 %0, %1, %2, %3;" : "=l"(d) : "l"(a), "l"(b), "l"(d));
}
__device__ __forceinline__ float lrelu(float z) { return z > 0.f ? z : 0.3f * z; }

__device__ float g_tmpH[28460160 + 1024];  // [4,1080,ws,3] interleaved
__device__ float g_img [10145112 + 1024];  // [4,3,hs,ws]  planar
__device__ float g_p1  [ 9500000];         // [4,10,h2,w2p] planar, padded rows
__device__ float g_c2  [14500000];         // [4,16,h3,w3p] planar, padded rows

struct Meta {
    int   hs[NS];
    float inv[NS], rinv[NS], scl[NS];
    int   offT[NS], offI[NS], offP[NS], offC[NS];
    int   w2p[NS], w3p[NS];
    int   offW[NS];
    int   wsum;
    int   noff[NS];
    int   ntot;
    int   bsRV[NS + 1], bsCP[NS + 1], bsC2[NS + 1], bsC3[NS + 1];
};

__device__ __forceinline__ int fscale(const int* bs)
{
    int k = 0;
#pragma unroll
    for (int i = 1; i < NS; i++)
        if ((int)blockIdx.x >= bs[i]) k = i;
    return k;
}

// ---------------------------------------------------------------------------
// Stage 1: horizontal antialiased resize, ALL scales fused.
// ---------------------------------------------------------------------------
__global__ void __launch_bounds__(256)
k_resize_h(const float* __restrict__ in, Meta m)
{
    __shared__ float srow[HIN * 3];
    int by = blockIdx.x;
    const float* rp = in + by * (HIN * 3);
    for (int i = threadIdx.x; i < HIN * 3; i += 256) srow[i] = rp[i];
    __syncthreads();

    for (int it = threadIdx.x; it < m.wsum; it += 256) {
        int k = 0;
#pragma unroll
        for (int i = 1; i < NS; i++)
            if (it >= m.offW[i]) k = i;
        int ox = it - m.offW[k];
        int ws = m.hs[k];
        float inv = m.inv[k], rinv = m.rinv[k];

        float sf = (ox + 0.5f) * inv - 0.5f;
        int j0 = (int)ceilf(sf - inv);  if (j0 < 0) j0 = 0;
        int j1 = (int)floorf(sf + inv); if (j1 > HIN - 1) j1 = HIN - 1;
        float a0 = 0.f, a1 = 0.f, a2 = 0.f, wsum = 0.f;
        const float* s = srow + j0 * 3;
        float fj = (float)j0;
        for (int j = j0; j <= j1; j++) {
            float wv = fmaxf(fmaf(fabsf(sf - fj), -rinv, 1.f), 0.f);
            wsum += wv;
            a0 = fmaf(wv, s[0], a0);
            a1 = fmaf(wv, s[1], a1);
            a2 = fmaf(wv, s[2], a2);
            s += 3; fj += 1.f;
        }
        float sc = 1.f / wsum;
        float* o = g_tmpH + m.offT[k] + (by * ws + ox) * 3;
        o[0] = a0 * sc; o[1] = a1 * sc; o[2] = a2 * sc;
    }
}

// ---------------------------------------------------------------------------
// Stage 2: vertical resize + (x-127.5)/128 -> planar img.
// 2 output rows per thread; shared taps, exact per-row windows.
// ---------------------------------------------------------------------------
__global__ void k_resize_v(Meta m)
{
    int k = fscale(m.bsRV);
    int hs = m.hs[k], ws = hs;
    int ph = (hs + 1) >> 1;
    float inv = m.inv[k], rinv = m.rinv[k];
    int idx = (blockIdx.x - m.bsRV[k]) * blockDim.x + threadIdx.x;
    if (idx >= BATCH * ph * ws) return;
    int x  = idx % ws;
    int t  = idx / ws;
    int p  = t % ph;
    int b  = t / ph;
    int oy0 = 2 * p;
    bool has1 = (oy0 + 1) < hs;

    float sf0 = (oy0 + 0.5f) * inv - 0.5f;
    float sf1 = (oy0 + 1.5f) * inv - 0.5f;
    float sfL = has1 ? sf1 : sf0;
    int j0 = (int)ceilf(sf0 - inv);  if (j0 < 0) j0 = 0;
    int j1 = (int)floorf(sfL + inv); if (j1 > HIN - 1) j1 = HIN - 1;
    int j1r0 = (int)floorf(sf0 + inv); if (j1r0 > HIN - 1) j1r0 = HIN - 1;
    int j0r1 = (int)ceilf(sf1 - inv);  if (j0r1 < 0) j0r1 = 0;

    float a00 = 0.f, a01 = 0.f, a02 = 0.f, ws0 = 0.f;
    float a10 = 0.f, a11 = 0.f, a12 = 0.f, ws1 = 0.f;
    const float* ptap = g_tmpH + m.offT[k] + ((b * HIN + j0) * ws + x) * 3;
    int step = ws * 3;
    float fj = (float)j0;
    for (int j = j0; j <= j1; j++) {
        float w0 = fmaxf(fmaf(fabsf(sf0 - fj), -rinv, 1.f), 0.f);
        float w1 = fmaxf(fmaf(fabsf(sf1 - fj), -rinv, 1.f), 0.f);
        if (j > j1r0) w0 = 0.f;
        if (j < j0r1) w1 = 0.f;
        float v0 = ptap[0], v1 = ptap[1], v2 = ptap[2];
        ws0 += w0; ws1 += w1;
        a00 = fmaf(w0, v0, a00);
        a01 = fmaf(w0, v1, a01);
        a02 = fmaf(w0, v2, a02);
        a10 = fmaf(w1, v0, a10);
        a11 = fmaf(w1, v1, a11);
        a12 = fmaf(w1, v2, a12);
        ptap += step; fj += 1.f;
    }

    int plane = hs * ws;
    float* ob = g_img + m.offI[k] + b * 3 * plane + oy0 * ws + x;
    {
        float s = 1.f / ws0;
        ob[0]         = (a00 * s - 127.5f) * (1.f / 128.f);
        ob[plane]     = (a01 * s - 127.5f) * (1.f / 128.f);
        ob[2 * plane] = (a02 * s - 127.5f) * (1.f / 128.f);
    }
    if (has1) {
        float s = 1.f / ws1;
        ob += ws;
        ob[0]         = (a10 * s - 127.5f) * (1.f / 128.f);
        ob[plane]     = (a11 * s - 127.5f) * (1.f / 128.f);
        ob[2 * plane] = (a12 * s - 127.5f) * (1.f / 128.f);
    }
}

// ---------------------------------------------------------------------------
// Stage 3: conv3x3 3->10 + lrelu fused with 2x2/2 maxpool.
// Writes g_p1 with padded row stride w2p.
// ---------------------------------------------------------------------------
__global__ void __launch_bounds__(128, 4)
k_conv1pool(const float* __restrict__ w, const float* __restrict__ bias, Meta m)
{
    __shared__ __align__(16) float ws_[27 * 12];
    __shared__ __align__(8)  float bs_[10];
    for (int i = threadIdx.x; i < 270; i += blockDim.x) {
        int e = i / 10, p = i - e * 10;
        ws_[e * 12 + p] = w[i];
    }
    if (threadIdx.x < 10) bs_[threadIdx.x] = bias[threadIdx.x];
    __syncthreads();

    int k = fscale(m.bsCP);
    int hs = m.hs[k], ws = hs;
    int h1 = hs - 2, w1 = ws - 2;
    int h2 = (h1 + 1) >> 1, w2 = (w1 + 1) >> 1;
    int idx = (blockIdx.x - m.bsCP[k]) * blockDim.x + threadIdx.x;
    if (idx >= BATCH * h2 * w2) return;
    int x = idx % w2;
    int t = idx / w2;
    int y = t % h2;
    int b = t / h2;
    int r0 = 2 * y, c0 = 2 * x;
    bool vr = (r0 + 1 < h1), vc = (c0 + 1 < w1);

    u64 acc[4][5];
    {
        const u64* bq = (const u64*)bs_;
#pragma unroll
        for (int p = 0; p < 4; p++) {
            u64 b0 = bq[0], b1 = bq[1], b2 = bq[2], b3 = bq[3], b4 = bq[4];
            acc[p][0] = b0; acc[p][1] = b1; acc[p][2] = b2; acc[p][3] = b3; acc[p][4] = b4;
        }
    }

    int plane = hs * ws;
    const float* imgb = g_img + m.offI[k] + b * 3 * plane;

#pragma unroll
    for (int ic = 0; ic < 3; ic++) {
        u64 pp[4][4];
#pragma unroll
        for (int i = 0; i < 4; i++) {
            int ry = r0 + i; if (ry > hs - 1) ry = hs - 1;
            const float* rp = imgb + ic * plane + ry * ws;
#pragma unroll
            for (int j = 0; j < 4; j++) {
                int cx = c0 + j; if (cx > ws - 1) cx = ws - 1;
                pp[i][j] = pack2(__ldg(rp + cx));
            }
        }
#pragma unroll
        for (int ky = 0; ky < 3; ky++)
#pragma unroll
        for (int kx = 0; kx < 3; kx++) {
            const float* wbase = ws_ + ((ky * 3 + kx) * 3 + ic) * 12;
            ulonglong2 w01 = *(const ulonglong2*)wbase;
            ulonglong2 w23 = *(const ulonglong2*)(wbase + 4);
            u64        w4  = *(const u64*)(wbase + 8);
            u64 wv[5] = { w01.x, w01.y, w23.x, w23.y, w4 };
#pragma unroll
            for (int q = 0; q < 5; q++) {
                ffma2(acc[0][q], pp[ky][kx],         wv[q]);
                ffma2(acc[1][q], pp[ky][kx + 1],     wv[q]);
                ffma2(acc[2][q], pp[ky + 1][kx],     wv[q]);
                ffma2(acc[3][q], pp[ky + 1][kx + 1], wv[q]);
            }
        }
    }

    int w2p = m.w2p[k];
    int oplane = h2 * w2p;
    float* ob = g_p1 + m.offP[k] + b * 10 * oplane + y * w2p + x;
#pragma unroll
    for (int q = 0; q < 5; q++) {
        float z0, z1, a0, a1, u0, u1;
        unpk(acc[0][q], z0, z1); a0 = lrelu(z0); a1 = lrelu(z1);
        if (vc) { unpk(acc[1][q], z0, z1); a0 = fmaxf(a0, lrelu(z0)); a1 = fmaxf(a1, lrelu(z1)); }
        if (vr) { unpk(acc[2][q], z0, z1); a0 = fmaxf(a0, lrelu(z0)); a1 = fmaxf(a1, lrelu(z1));
            if (vc) { unpk(acc[3][q], u0, u1); a0 = fmaxf(a0, lrelu(u0)); a1 = fmaxf(a1, lrelu(u1)); } }
        ob[(2 * q)     * oplane] = a0;
        ob[(2 * q + 1) * oplane] = a1;
    }
}

// ---------------------------------------------------------------------------
// Stage 4: conv3x3 10->16 + lrelu. TX=4, double-buffered, vectorized loads
// (float4+float2 per (ky,ic); padded rows, no clamps).
// ---------------------------------------------------------------------------
__global__ void __launch_bounds__(128, 4)
k_conv2(const float* __restrict__ w, const float* __restrict__ bias, Meta m)
{
    __shared__ __align__(16) float ws_[1440];
    __shared__ __align__(8)  float bs_[16];
    {
        const float4* s4 = (const float4*)w;
        float4* d4 = (float4*)ws_;
        for (int i = threadIdx.x; i < 360; i += blockDim.x) d4[i] = s4[i];
        if (threadIdx.x < 16) bs_[threadIdx.x] = bias[threadIdx.x];
    }
    __syncthreads();

    int k = fscale(m.bsC2);
    int hs = m.hs[k];
    int hin = (hs - 1) >> 1, win = hin;
    int w2p = m.w2p[k];
    int hout = hin - 2, wout = win - 2;
    int WG = (wout + 3) >> 2;
    int idx = (blockIdx.x - m.bsC2[k]) * blockDim.x + threadIdx.x;
    if (idx >= BATCH * hout * WG) return;
    int xg = idx % WG;
    int t2 = idx / WG;
    int y  = t2 % hout;
    int b  = t2 / hout;
    int x0 = xg * 4;

    u64 acc[4][8];
    {
        const u64* bq = (const u64*)bs_;
#pragma unroll
        for (int q = 0; q < 8; q++) {
            u64 bv = bq[q];
            acc[0][q] = bv; acc[1][q] = bv; acc[2][q] = bv; acc[3][q] = bv;
        }
    }

    int plane = hin * w2p;
    const float* pb = g_p1 + m.offP[k] + b * 10 * plane + x0;

#pragma unroll
    for (int ky = 0; ky < 3; ky++) {
        const float* rbase = pb + (y + ky) * w2p;
        u64 vbuf[2][6];
        {
            float4 f4 = __ldg((const float4*)rbase);
            float2 f2 = __ldg((const float2*)(rbase + 4));
            vbuf[0][0] = pack2(f4.x); vbuf[0][1] = pack2(f4.y);
            vbuf[0][2] = pack2(f4.z); vbuf[0][3] = pack2(f4.w);
            vbuf[0][4] = pack2(f2.x); vbuf[0][5] = pack2(f2.y);
        }
#pragma unroll 2
        for (int ic = 0; ic < 10; ic++) {
            int cur = ic & 1;
            if (ic < 9) {
                const float* rn = rbase + (ic + 1) * plane;
                float4 f4 = __ldg((const float4*)rn);
                float2 f2 = __ldg((const float2*)(rn + 4));
                int nx = cur ^ 1;
                vbuf[nx][0] = pack2(f4.x); vbuf[nx][1] = pack2(f4.y);
                vbuf[nx][2] = pack2(f4.z); vbuf[nx][3] = pack2(f4.w);
                vbuf[nx][4] = pack2(f2.x); vbuf[nx][5] = pack2(f2.y);
            }
#pragma unroll
            for (int kx = 0; kx < 3; kx++) {
                const ulonglong2* wq = (const ulonglong2*)(ws_ + ((ky * 3 + kx) * 10 + ic) * 16);
#pragma unroll
                for (int q2 = 0; q2 < 4; q2++) {
                    ulonglong2 wv = wq[q2];
#pragma unroll
                    for (int t = 0; t < 4; t++) {
                        ffma2(acc[t][2 * q2 + 0], vbuf[cur][t + kx], wv.x);
                        ffma2(acc[t][2 * q2 + 1], vbuf[cur][t + kx], wv.y);
                    }
                }
            }
        }
    }

    int w3p = m.w3p[k];
    int oplane = hout * w3p;
    float* ob = g_c2 + m.offC[k] + b * 16 * oplane + y * w3p;
#pragma unroll
    for (int t = 0; t < 4; t++) {
        int x = x0 + t;
        if (x < wout) {
#pragma unroll
            for (int q = 0; q < 8; q++) {
                float z0, z1;
                unpk(acc[t][q], z0, z1);
                ob[(2 * q)     * oplane + x] = lrelu(z0);
                ob[(2 * q + 1) * oplane + x] = lrelu(z1);
            }
        }
    }
}

// ---------------------------------------------------------------------------
// Stage 5: conv3x3 16->32 + lrelu + heads + boxes + mask. TX=2 (R9 shape),
// double-buffered, vectorized loads (2x float2; padded rows, no clamps).
// Output layout: boxes[4][N][5] | reg[4][N][4] | mask[4][N]
// ---------------------------------------------------------------------------
__global__ void __launch_bounds__(128, 4)
k_conv3head(const float* __restrict__ w, const float* __restrict__ bias,
            const float* __restrict__ wp, const float* __restrict__ bp,
            const float* __restrict__ wr, const float* __restrict__ br,
            float* __restrict__ out, Meta m)
{
    __shared__ __align__(16) float ws_[4608];
    __shared__ __align__(8)  float cb_[32], hwp[64], hwr[128], hb[6];
    {
        const float4* s4 = (const float4*)w;
        float4* d4 = (float4*)ws_;
        for (int i = threadIdx.x; i < 1152; i += blockDim.x) d4[i] = s4[i];
        if (threadIdx.x < 32) cb_[threadIdx.x] = bias[threadIdx.x];
        if (threadIdx.x < 64) hwp[threadIdx.x] = wp[threadIdx.x];
        hwr[threadIdx.x] = wr[threadIdx.x];
        if (threadIdx.x == 64) { hb[0] = bp[0]; hb[1] = bp[1]; }
        if (threadIdx.x == 65) { hb[2] = br[0]; hb[3] = br[1]; hb[4] = br[2]; hb[5] = br[3]; }
    }
    __syncthreads();

    int k = fscale(m.bsC3);
    int hs = m.hs[k];
    int hin = ((hs - 1) >> 1) - 2, win = hin;
    int w3p = m.w3p[k];
    int hout = hin - 2, wout = win - 2;
    int WG = (wout + 1) >> 1;
    int idx = (blockIdx.x - m.bsC3[k]) * blockDim.x + threadIdx.x;
    if (idx >= BATCH * hout * WG) return;
    int xg = idx % WG;
    int t2 = idx / WG;
    int y  = t2 % hout;
    int b  = t2 / hout;
    int x0 = xg * 2;

    u64 acc[2][16];
    {
        const u64* bq = (const u64*)cb_;
#pragma unroll
        for (int q = 0; q < 16; q++) {
            u64 bv = bq[q];
            acc[0][q] = bv; acc[1][q] = bv;
        }
    }

    int plane = hin * w3p;
    const float* cb = g_c2 + m.offC[k] + b * 16 * plane + x0;

#pragma unroll
    for (int ky = 0; ky < 3; ky++) {
        const float* rbase = cb + (y + ky) * w3p;
        u64 vbuf[2][4];
        {
            float2 fa = __ldg((const float2*)rbase);
            float2 fb = __ldg((const float2*)(rbase + 2));
            vbuf[0][0] = pack2(fa.x); vbuf[0][1] = pack2(fa.y);
            vbuf[0][2] = pack2(fb.x); vbuf[0][3] = pack2(fb.y);
        }
#pragma unroll 2
        for (int ic = 0; ic < 16; ic++) {
            int cur = ic & 1;
            if (ic < 15) {
                const float* rn = rbase + (ic + 1) * plane;
                float2 fa = __ldg((const float2*)rn);
                float2 fb = __ldg((const float2*)(rn + 2));
                int nx = cur ^ 1;
                vbuf[nx][0] = pack2(fa.x); vbuf[nx][1] = pack2(fa.y);
                vbuf[nx][2] = pack2(fb.x); vbuf[nx][3] = pack2(fb.y);
            }
#pragma unroll
            for (int kx = 0; kx < 3; kx++) {
                const ulonglong2* wq = (const ulonglong2*)(ws_ + ((ky * 3 + kx) * 16 + ic) * 32);
#pragma unroll
                for (int q2 = 0; q2 < 8; q2++) {
                    ulonglong2 wv = wq[q2];
                    ffma2(acc[0][2 * q2 + 0], vbuf[cur][kx],     wv.x);
                    ffma2(acc[0][2 * q2 + 1], vbuf[cur][kx],     wv.y);
                    ffma2(acc[1][2 * q2 + 0], vbuf[cur][kx + 1], wv.x);
                    ffma2(acc[1][2 * q2 + 1], vbuf[cur][kx + 1], wv.y);
                }
            }
        }
    }

    int ntot = m.ntot;
    float scale = m.scl[k];
    int nbase = m.noff[k] + y * wout;
    float fy = (float)y;
    const u64* wp64 = (const u64*)hwp;
    const u64* wr64 = (const u64*)hwr;

#pragma unroll
    for (int t = 0; t < 2; t++) {
        int x = x0 + t;
        if (x >= wout) continue;

        u64 zz = pk2(hb[0], hb[1]);
        u64 rA = pk2(hb[2], hb[3]);
        u64 rB = pk2(hb[4], hb[5]);
#pragma unroll
        for (int q = 0; q < 16; q++) {
            float z0, z1;
            unpk(acc[t][q], z0, z1);
            u64 v0 = pack2(lrelu(z0));
            u64 v1 = pack2(lrelu(z1));
            int c0 = 2 * q, c1 = 2 * q + 1;
            ffma2(zz, v0, wp64[c0]);         ffma2(zz, v1, wp64[c1]);
            ffma2(rA, v0, wr64[2 * c0]);     ffma2(rA, v1, wr64[2 * c1]);
            ffma2(rB, v0, wr64[2 * c0 + 1]); ffma2(rB, v1, wr64[2 * c1 + 1]);
        }
        float z0, z1, r0, r1, r2, r3;
        unpk(zz, z0, z1);
        unpk(rA, r0, r1);
        unpk(rB, r2, r3);
        float score = 1.f / (1.f + expf(z0 - z1));

        int n = nbase + x;
        float fx = (float)x;
        float ulr = rintf((fy * 2.f + 1.f)  / scale);
        float ulc = rintf((fx * 2.f + 1.f)  / scale);
        float drr = rintf((fy * 2.f + 12.f) / scale);
        float drc = rintf((fx * 2.f + 12.f) / scale);

        float* pbx = out + (b * ntot + n) * 5;
        pbx[0] = ulr; pbx[1] = ulc; pbx[2] = drr; pbx[3] = drc; pbx[4] = score;

        float* prg = out + BATCH * ntot * 5 + (b * ntot + n) * 4;
        prg[0] = r0; prg[1] = r1; prg[2] = r2; prg[3] = r3;

        out[BATCH * ntot * 9 + b * ntot + n] = (score >= 0.6f) ? 1.f : 0.f;
    }
}

// ---------------------------------------------------------------------------
extern "C" void kernel_launch(void* const* d_in, const int* in_sizes, int n_in,
                              void* d_out, int out_size)
{
    const float* inp = (const float*)d_in[0];
    const float* w1  = (const float*)d_in[1];
    const float* b1  = (const float*)d_in[2];
    const float* w2  = (const float*)d_in[3];
    const float* b2  = (const float*)d_in[4];
    const float* w3  = (const float*)d_in[5];
    const float* b3  = (const float*)d_in[6];
    const float* wp  = (const float*)d_in[7];
    const float* bp  = (const float*)d_in[8];
    const float* wr  = (const float*)d_in[9];
    const float* br  = (const float*)d_in[10];
    float* out = (float*)d_out;
    (void)in_sizes; (void)n_in; (void)out_size;

    Meta m;
    int ns = 0;
    {
        double s = 12.0 / 20.0, mm = s * 1080.0;
        while (mm >= 12.0 && ns < NS) {
            m.hs[ns]   = (int)ceil(1080.0 * s);
            m.inv[ns]  = (float)(1080.0 / (double)m.hs[ns]);
            m.rinv[ns] = (float)((double)m.hs[ns] / 1080.0);
            m.scl[ns]  = (float)s;
            ns++;
            s *= 0.709; mm *= 0.709;
        }
    }

    int oT = 0, oI = 0, oP = 0, oC = 0, oW = 0, ntot = 0;
    m.bsRV[0] = m.bsCP[0] = m.bsC2[0] = m.bsC3[0] = 0;
    for (int k = 0; k < ns; k++) {
        int hs = m.hs[k], ws = hs;
        int h1 = hs - 2;
        int h2 = (h1 + 1) / 2, w2d = h2;
        int h3 = h2 - 2, w3d = h3;
        int h4 = h3 - 2, w4 = h4;
        int ph = (hs + 1) / 2;

        int w2p = (w2d + 11) & ~3;          // padded p1 row stride
        int w3p = (w3d + 11) & ~3;          // padded c2 row stride
        m.w2p[k] = w2p;
        m.w3p[k] = w3p;

        m.offT[k] = oT;  oT += BATCH * HIN * ws * 3;
        m.offI[k] = oI;  oI += BATCH * hs * ws * 3;
        m.offP[k] = oP;  oP += BATCH * h2 * w2p * 10;
        m.offC[k] = oC;  oC += BATCH * h3 * w3p * 16;
        m.offW[k] = oW;  oW += ws;
        m.noff[k] = ntot; ntot += h4 * w4;

        int T;
        T = BATCH * ph * ws;                   m.bsRV[k+1] = m.bsRV[k] + (T + 255) / 256;
        T = BATCH * h2 * w2d;                  m.bsCP[k+1] = m.bsCP[k] + (T + 127) / 128;
        T = BATCH * h3 * ((w3d + 3) / 4);      m.bsC2[k+1] = m.bsC2[k] + (T + 127) / 128;
        T = BATCH * h4 * ((w4 + 1) / 2);       m.bsC3[k+1] = m.bsC3[k] + (T + 127) / 128;
    }
    m.ntot = ntot;
    m.wsum = oW;
    for (int k = ns; k < NS; k++) {
        m.hs[k] = m.hs[ns-1]; m.inv[k] = m.inv[ns-1];
        m.rinv[k] = m.rinv[ns-1]; m.scl[k] = m.scl[ns-1];
        m.offT[k] = m.offI[k] = m.offP[k] = m.offC[k] = 0; m.noff[k] = 0;
        m.w2p[k] = 16; m.w3p[k] = 16;
        m.bsRV[k+1] = m.bsRV[k];
        m.bsCP[k+1] = m.bsCP[k]; m.bsC2[k+1] = m.bsC2[k]; m.bsC3[k+1] = m.bsC3[k];
        m.offW[k] = 0x7fffffff;
        m.bsRV[k] = 0x7fffffff; m.bsCP[k] = 0x7fffffff;
        m.bsC2[k] = 0x7fffffff; m.bsC3[k] = 0x7fffffff;
    }

    k_resize_h <<<BATCH * HIN, 256>>>(inp, m);
    k_resize_v <<<m.bsRV[ns], 256>>>(m);
    k_conv1pool<<<m.bsCP[ns], 128>>>(w1, b1, m);
    k_conv2    <<<m.bsC2[ns], 128>>>(w2, b2, m);
    k_conv3head<<<m.bsC3[ns], 128>>>(w3, b3, wp, bp, wr, br, out, m);
}

// round 16
// speedup vs baseline: 1.0860x; 1.0221x over previous
#include <cuda_runtime.h>
#include <math.h>

// ---------------------------------------------------------------------------
// MTCNN P-net pyramid, B=4, 1080x1080x3, 12 scales.  R15 = R14 +
//  - g_img rows padded to even stride (wsP): conv1pool input loads become
//    2x float2 per row with NO clamp ALU (over-reads land in padding and are
//    discarded by the existing vr/vc gates)
//  - conv2: full unroll of the ic loop (scheduling experiment; conv3head
//    kept at unroll 2 as control)
// Stages: resize_h(all scales) | resize_v | conv1+pool | conv2 | conv3+heads
// ---------------------------------------------------------------------------

#define BATCH 4
#define HIN 1080
#define NS 12

typedef unsigned long long u64;

__device__ __forceinline__ u64 pack2(float x) {
    u64 r; asm("mov.b64 %0, {%1, %1};" : "=l"(r) : "f"(x)); return r;
}
__device__ __forceinline__ u64 pk2(float lo, float hi) {
    u64 r; asm("mov.b64 %0, {%1, %2};" : "=l"(r) : "f"(lo), "f"(hi)); return r;
}
__device__ __forceinline__ void unpk(u64 v, float& lo, float& hi) {
    asm("mov.b64 {%0, %1}, %2;" : "=f"(lo), "=f"(hi) : "l"(v));
}
__device__ __forceinline__ void ffma2(u64& d, u64 a, u64 b) {
    asm("fma.rn.f32x2 %0, %1, %2, %3;" : "=l"(d) : "l"(a), "l"(b), "l"(d));
}
__device__ __forceinline__ float lrelu(float z) { return z > 0.f ? z : 0.3f * z; }

__device__ float g_tmpH[28460160 + 1024];  // [4,1080,ws,3] interleaved
__device__ float g_img [10250000];         // [4,3,hs,wsP] planar, padded rows
__device__ float g_p1  [ 9500000];         // [4,10,h2,w2p] planar, padded rows
__device__ float g_c2  [14500000];         // [4,16,h3,w3p] planar, padded rows

struct Meta {
    int   hs[NS];
    float inv[NS], rinv[NS], scl[NS];
    int   offT[NS], offI[NS], offP[NS], offC[NS];
    int   wsP[NS], w2p[NS], w3p[NS];
    int   offW[NS];
    int   wsum;
    int   noff[NS];
    int   ntot;
    int   bsRV[NS + 1], bsCP[NS + 1], bsC2[NS + 1], bsC3[NS + 1];
};

__device__ __forceinline__ int fscale(const int* bs)
{
    int k = 0;
#pragma unroll
    for (int i = 1; i < NS; i++)
        if ((int)blockIdx.x >= bs[i]) k = i;
    return k;
}

// ---------------------------------------------------------------------------
// Stage 1: horizontal antialiased resize, ALL scales fused.
// ---------------------------------------------------------------------------
__global__ void __launch_bounds__(256)
k_resize_h(const float* __restrict__ in, Meta m)
{
    __shared__ float srow[HIN * 3];
    int by = blockIdx.x;
    const float* rp = in + by * (HIN * 3);
    for (int i = threadIdx.x; i < HIN * 3; i += 256) srow[i] = rp[i];
    __syncthreads();

    for (int it = threadIdx.x; it < m.wsum; it += 256) {
        int k = 0;
#pragma unroll
        for (int i = 1; i < NS; i++)
            if (it >= m.offW[i]) k = i;
        int ox = it - m.offW[k];
        int ws = m.hs[k];
        float inv = m.inv[k], rinv = m.rinv[k];

        float sf = (ox + 0.5f) * inv - 0.5f;
        int j0 = (int)ceilf(sf - inv);  if (j0 < 0) j0 = 0;
        int j1 = (int)floorf(sf + inv); if (j1 > HIN - 1) j1 = HIN - 1;
        float a0 = 0.f, a1 = 0.f, a2 = 0.f, wsum = 0.f;
        const float* s = srow + j0 * 3;
        float fj = (float)j0;
        for (int j = j0; j <= j1; j++) {
            float wv = fmaxf(fmaf(fabsf(sf - fj), -rinv, 1.f), 0.f);
            wsum += wv;
            a0 = fmaf(wv, s[0], a0);
            a1 = fmaf(wv, s[1], a1);
            a2 = fmaf(wv, s[2], a2);
            s += 3; fj += 1.f;
        }
        float sc = 1.f / wsum;
        float* o = g_tmpH + m.offT[k] + (by * ws + ox) * 3;
        o[0] = a0 * sc; o[1] = a1 * sc; o[2] = a2 * sc;
    }
}

// ---------------------------------------------------------------------------
// Stage 2: vertical resize + (x-127.5)/128 -> planar img (padded rows).
// 2 output rows per thread; shared taps, exact per-row windows.
// ---------------------------------------------------------------------------
__global__ void k_resize_v(Meta m)
{
    int k = fscale(m.bsRV);
    int hs = m.hs[k], ws = hs;
    int wsP = m.wsP[k];
    int ph = (hs + 1) >> 1;
    float inv = m.inv[k], rinv = m.rinv[k];
    int idx = (blockIdx.x - m.bsRV[k]) * blockDim.x + threadIdx.x;
    if (idx >= BATCH * ph * ws) return;
    int x  = idx % ws;
    int t  = idx / ws;
    int p  = t % ph;
    int b  = t / ph;
    int oy0 = 2 * p;
    bool has1 = (oy0 + 1) < hs;

    float sf0 = (oy0 + 0.5f) * inv - 0.5f;
    float sf1 = (oy0 + 1.5f) * inv - 0.5f;
    float sfL = has1 ? sf1 : sf0;
    int j0 = (int)ceilf(sf0 - inv);  if (j0 < 0) j0 = 0;
    int j1 = (int)floorf(sfL + inv); if (j1 > HIN - 1) j1 = HIN - 1;
    int j1r0 = (int)floorf(sf0 + inv); if (j1r0 > HIN - 1) j1r0 = HIN - 1;
    int j0r1 = (int)ceilf(sf1 - inv);  if (j0r1 < 0) j0r1 = 0;

    float a00 = 0.f, a01 = 0.f, a02 = 0.f, ws0 = 0.f;
    float a10 = 0.f, a11 = 0.f, a12 = 0.f, ws1 = 0.f;
    const float* ptap = g_tmpH + m.offT[k] + ((b * HIN + j0) * ws + x) * 3;
    int step = ws * 3;
    float fj = (float)j0;
    for (int j = j0; j <= j1; j++) {
        float w0 = fmaxf(fmaf(fabsf(sf0 - fj), -rinv, 1.f), 0.f);
        float w1 = fmaxf(fmaf(fabsf(sf1 - fj), -rinv, 1.f), 0.f);
        if (j > j1r0) w0 = 0.f;
        if (j < j0r1) w1 = 0.f;
        float v0 = ptap[0], v1 = ptap[1], v2 = ptap[2];
        ws0 += w0; ws1 += w1;
        a00 = fmaf(w0, v0, a00);
        a01 = fmaf(w0, v1, a01);
        a02 = fmaf(w0, v2, a02);
        a10 = fmaf(w1, v0, a10);
        a11 = fmaf(w1, v1, a11);
        a12 = fmaf(w1, v2, a12);
        ptap += step; fj += 1.f;
    }

    int plane = hs * wsP;
    float* ob = g_img + m.offI[k] + b * 3 * plane + oy0 * wsP + x;
    {
        float s = 1.f / ws0;
        ob[0]         = (a00 * s - 127.5f) * (1.f / 128.f);
        ob[plane]     = (a01 * s - 127.5f) * (1.f / 128.f);
        ob[2 * plane] = (a02 * s - 127.5f) * (1.f / 128.f);
    }
    if (has1) {
        float s = 1.f / ws1;
        ob += wsP;
        ob[0]         = (a10 * s - 127.5f) * (1.f / 128.f);
        ob[plane]     = (a11 * s - 127.5f) * (1.f / 128.f);
        ob[2 * plane] = (a12 * s - 127.5f) * (1.f / 128.f);
    }
}

// ---------------------------------------------------------------------------
// Stage 3: conv3x3 3->10 + lrelu fused with 2x2/2 maxpool.
// Vectorized float2 input loads (even padded rows, no clamps).
// ---------------------------------------------------------------------------
__global__ void __launch_bounds__(128, 4)
k_conv1pool(const float* __restrict__ w, const float* __restrict__ bias, Meta m)
{
    __shared__ __align__(16) float ws_[27 * 12];
    __shared__ __align__(8)  float bs_[10];
    for (int i = threadIdx.x; i < 270; i += blockDim.x) {
        int e = i / 10, p = i - e * 10;
        ws_[e * 12 + p] = w[i];
    }
    if (threadIdx.x < 10) bs_[threadIdx.x] = bias[threadIdx.x];
    __syncthreads();

    int k = fscale(m.bsCP);
    int hs = m.hs[k], ws = hs;
    int wsP = m.wsP[k];
    int h1 = hs - 2, w1 = ws - 2;
    int h2 = (h1 + 1) >> 1, w2 = (w1 + 1) >> 1;
    int idx = (blockIdx.x - m.bsCP[k]) * blockDim.x + threadIdx.x;
    if (idx >= BATCH * h2 * w2) return;
    int x = idx % w2;
    int t = idx / w2;
    int y = t % h2;
    int b = t / h2;
    int r0 = 2 * y, c0 = 2 * x;
    bool vr = (r0 + 1 < h1), vc = (c0 + 1 < w1);

    u64 acc[4][5];
    {
        const u64* bq = (const u64*)bs_;
#pragma unroll
        for (int p = 0; p < 4; p++) {
            u64 b0 = bq[0], b1 = bq[1], b2 = bq[2], b3 = bq[3], b4 = bq[4];
            acc[p][0] = b0; acc[p][1] = b1; acc[p][2] = b2; acc[p][3] = b3; acc[p][4] = b4;
        }
    }

    int plane = hs * wsP;
    const float* imgb = g_img + m.offI[k] + b * 3 * plane + r0 * wsP + c0;

#pragma unroll
    for (int ic = 0; ic < 3; ic++) {
        u64 pp[4][4];
        const float* rp = imgb + ic * plane;
#pragma unroll
        for (int i = 0; i < 4; i++) {
            float2 fa = __ldg((const float2*)rp);
            float2 fb = __ldg((const float2*)(rp + 2));
            pp[i][0] = pack2(fa.x); pp[i][1] = pack2(fa.y);
            pp[i][2] = pack2(fb.x); pp[i][3] = pack2(fb.y);
            rp += wsP;
        }
#pragma unroll
        for (int ky = 0; ky < 3; ky++)
#pragma unroll
        for (int kx = 0; kx < 3; kx++) {
            const float* wbase = ws_ + ((ky * 3 + kx) * 3 + ic) * 12;
            ulonglong2 w01 = *(const ulonglong2*)wbase;
            ulonglong2 w23 = *(const ulonglong2*)(wbase + 4);
            u64        w4  = *(const u64*)(wbase + 8);
            u64 wv[5] = { w01.x, w01.y, w23.x, w23.y, w4 };
#pragma unroll
            for (int q = 0; q < 5; q++) {
                ffma2(acc[0][q], pp[ky][kx],         wv[q]);
                ffma2(acc[1][q], pp[ky][kx + 1],     wv[q]);
                ffma2(acc[2][q], pp[ky + 1][kx],     wv[q]);
                ffma2(acc[3][q], pp[ky + 1][kx + 1], wv[q]);
            }
        }
    }

    int w2p = m.w2p[k];
    int oplane = h2 * w2p;
    float* ob = g_p1 + m.offP[k] + b * 10 * oplane + y * w2p + x;
#pragma unroll
    for (int q = 0; q < 5; q++) {
        float z0, z1, a0, a1, u0, u1;
        unpk(acc[0][q], z0, z1); a0 = lrelu(z0); a1 = lrelu(z1);
        if (vc) { unpk(acc[1][q], z0, z1); a0 = fmaxf(a0, lrelu(z0)); a1 = fmaxf(a1, lrelu(z1)); }
        if (vr) { unpk(acc[2][q], z0, z1); a0 = fmaxf(a0, lrelu(z0)); a1 = fmaxf(a1, lrelu(z1));
            if (vc) { unpk(acc[3][q], u0, u1); a0 = fmaxf(a0, lrelu(u0)); a1 = fmaxf(a1, lrelu(u1)); } }
        ob[(2 * q)     * oplane] = a0;
        ob[(2 * q + 1) * oplane] = a1;
    }
}

// ---------------------------------------------------------------------------
// Stage 4: conv3x3 10->16 + lrelu. TX=4, double-buffered, vectorized loads,
// FULL unroll of ic loop (scheduling experiment).
// ---------------------------------------------------------------------------
__global__ void __launch_bounds__(128, 4)
k_conv2(const float* __restrict__ w, const float* __restrict__ bias, Meta m)
{
    __shared__ __align__(16) float ws_[1440];
    __shared__ __align__(8)  float bs_[16];
    {
        const float4* s4 = (const float4*)w;
        float4* d4 = (float4*)ws_;
        for (int i = threadIdx.x; i < 360; i += blockDim.x) d4[i] = s4[i];
        if (threadIdx.x < 16) bs_[threadIdx.x] = bias[threadIdx.x];
    }
    __syncthreads();

    int k = fscale(m.bsC2);
    int hs = m.hs[k];
    int hin = (hs - 1) >> 1, win = hin;
    int w2p = m.w2p[k];
    int hout = hin - 2, wout = win - 2;
    int WG = (wout + 3) >> 2;
    int idx = (blockIdx.x - m.bsC2[k]) * blockDim.x + threadIdx.x;
    if (idx >= BATCH * hout * WG) return;
    int xg = idx % WG;
    int t2 = idx / WG;
    int y  = t2 % hout;
    int b  = t2 / hout;
    int x0 = xg * 4;

    u64 acc[4][8];
    {
        const u64* bq = (const u64*)bs_;
#pragma unroll
        for (int q = 0; q < 8; q++) {
            u64 bv = bq[q];
            acc[0][q] = bv; acc[1][q] = bv; acc[2][q] = bv; acc[3][q] = bv;
        }
    }

    int plane = hin * w2p;
    const float* pb = g_p1 + m.offP[k] + b * 10 * plane + x0;

#pragma unroll
    for (int ky = 0; ky < 3; ky++) {
        const float* rbase = pb + (y + ky) * w2p;
        u64 vbuf[2][6];
        {
            float4 f4 = __ldg((const float4*)rbase);
            float2 f2 = __ldg((const float2*)(rbase + 4));
            vbuf[0][0] = pack2(f4.x); vbuf[0][1] = pack2(f4.y);
            vbuf[0][2] = pack2(f4.z); vbuf[0][3] = pack2(f4.w);
            vbuf[0][4] = pack2(f2.x); vbuf[0][5] = pack2(f2.y);
        }
#pragma unroll
        for (int ic = 0; ic < 10; ic++) {
            int cur = ic & 1;
            if (ic < 9) {
                const float* rn = rbase + (ic + 1) * plane;
                float4 f4 = __ldg((const float4*)rn);
                float2 f2 = __ldg((const float2*)(rn + 4));
                int nx = cur ^ 1;
                vbuf[nx][0] = pack2(f4.x); vbuf[nx][1] = pack2(f4.y);
                vbuf[nx][2] = pack2(f4.z); vbuf[nx][3] = pack2(f4.w);
                vbuf[nx][4] = pack2(f2.x); vbuf[nx][5] = pack2(f2.y);
            }
#pragma unroll
            for (int kx = 0; kx < 3; kx++) {
                const ulonglong2* wq = (const ulonglong2*)(ws_ + ((ky * 3 + kx) * 10 + ic) * 16);
#pragma unroll
                for (int q2 = 0; q2 < 4; q2++) {
                    ulonglong2 wv = wq[q2];
#pragma unroll
                    for (int t = 0; t < 4; t++) {
                        ffma2(acc[t][2 * q2 + 0], vbuf[cur][t + kx], wv.x);
                        ffma2(acc[t][2 * q2 + 1], vbuf[cur][t + kx], wv.y);
                    }
                }
            }
        }
    }

    int w3p = m.w3p[k];
    int oplane = hout * w3p;
    float* ob = g_c2 + m.offC[k] + b * 16 * oplane + y * w3p;
#pragma unroll
    for (int t = 0; t < 4; t++) {
        int x = x0 + t;
        if (x < wout) {
#pragma unroll
            for (int q = 0; q < 8; q++) {
                float z0, z1;
                unpk(acc[t][q], z0, z1);
                ob[(2 * q)     * oplane + x] = lrelu(z0);
                ob[(2 * q + 1) * oplane + x] = lrelu(z1);
            }
        }
    }
}

// ---------------------------------------------------------------------------
// Stage 5: conv3x3 16->32 + lrelu + heads + boxes + mask. TX=2,
// double-buffered, vectorized loads (unroll 2 control).
// Output layout: boxes[4][N][5] | reg[4][N][4] | mask[4][N]
// ---------------------------------------------------------------------------
__global__ void __launch_bounds__(128, 4)
k_conv3head(const float* __restrict__ w, const float* __restrict__ bias,
            const float* __restrict__ wp, const float* __restrict__ bp,
            const float* __restrict__ wr, const float* __restrict__ br,
            float* __restrict__ out, Meta m)
{
    __shared__ __align__(16) float ws_[4608];
    __shared__ __align__(8)  float cb_[32], hwp[64], hwr[128], hb[6];
    {
        const float4* s4 = (const float4*)w;
        float4* d4 = (float4*)ws_;
        for (int i = threadIdx.x; i < 1152; i += blockDim.x) d4[i] = s4[i];
        if (threadIdx.x < 32) cb_[threadIdx.x] = bias[threadIdx.x];
        if (threadIdx.x < 64) hwp[threadIdx.x] = wp[threadIdx.x];
        hwr[threadIdx.x] = wr[threadIdx.x];
        if (threadIdx.x == 64) { hb[0] = bp[0]; hb[1] = bp[1]; }
        if (threadIdx.x == 65) { hb[2] = br[0]; hb[3] = br[1]; hb[4] = br[2]; hb[5] = br[3]; }
    }
    __syncthreads();

    int k = fscale(m.bsC3);
    int hs = m.hs[k];
    int hin = ((hs - 1) >> 1) - 2, win = hin;
    int w3p = m.w3p[k];
    int hout = hin - 2, wout = win - 2;
    int WG = (wout + 1) >> 1;
    int idx = (blockIdx.x - m.bsC3[k]) * blockDim.x + threadIdx.x;
    if (idx >= BATCH * hout * WG) return;
    int xg = idx % WG;
    int t2 = idx / WG;
    int y  = t2 % hout;
    int b  = t2 / hout;
    int x0 = xg * 2;

    u64 acc[2][16];
    {
        const u64* bq = (const u64*)cb_;
#pragma unroll
        for (int q = 0; q < 16; q++) {
            u64 bv = bq[q];
            acc[0][q] = bv; acc[1][q] = bv;
        }
    }

    int plane = hin * w3p;
    const float* cb = g_c2 + m.offC[k] + b * 16 * plane + x0;

#pragma unroll
    for (int ky = 0; ky < 3; ky++) {
        const float* rbase = cb + (y + ky) * w3p;
        u64 vbuf[2][4];
        {
            float2 fa = __ldg((const float2*)rbase);
            float2 fb = __ldg((const float2*)(rbase + 2));
            vbuf[0][0] = pack2(fa.x); vbuf[0][1] = pack2(fa.y);
            vbuf[0][2] = pack2(fb.x); vbuf[0][3] = pack2(fb.y);
        }
#pragma unroll 2
        for (int ic = 0; ic < 16; ic++) {
            int cur = ic & 1;
            if (ic < 15) {
                const float* rn = rbase + (ic + 1) * plane;
                float2 fa = __ldg((const float2*)rn);
                float2 fb = __ldg((const float2*)(rn + 2));
                int nx = cur ^ 1;
                vbuf[nx][0] = pack2(fa.x); vbuf[nx][1] = pack2(fa.y);
                vbuf[nx][2] = pack2(fb.x); vbuf[nx][3] = pack2(fb.y);
            }
#pragma unroll
            for (int kx = 0; kx < 3; kx++) {
                const ulonglong2* wq = (const ulonglong2*)(ws_ + ((ky * 3 + kx) * 16 + ic) * 32);
#pragma unroll
                for (int q2 = 0; q2 < 8; q2++) {
                    ulonglong2 wv = wq[q2];
                    ffma2(acc[0][2 * q2 + 0], vbuf[cur][kx],     wv.x);
                    ffma2(acc[0][2 * q2 + 1], vbuf[cur][kx],     wv.y);
                    ffma2(acc[1][2 * q2 + 0], vbuf[cur][kx + 1], wv.x);
                    ffma2(acc[1][2 * q2 + 1], vbuf[cur][kx + 1], wv.y);
                }
            }
        }
    }

    int ntot = m.ntot;
    float scale = m.scl[k];
    int nbase = m.noff[k] + y * wout;
    float fy = (float)y;
    const u64* wp64 = (const u64*)hwp;
    const u64* wr64 = (const u64*)hwr;

#pragma unroll
    for (int t = 0; t < 2; t++) {
        int x = x0 + t;
        if (x >= wout) continue;

        u64 zz = pk2(hb[0], hb[1]);
        u64 rA = pk2(hb[2], hb[3]);
        u64 rB = pk2(hb[4], hb[5]);
#pragma unroll
        for (int q = 0; q < 16; q++) {
            float z0, z1;
            unpk(acc[t][q], z0, z1);
            u64 v0 = pack2(lrelu(z0));
            u64 v1 = pack2(lrelu(z1));
            int c0 = 2 * q, c1 = 2 * q + 1;
            ffma2(zz, v0, wp64[c0]);         ffma2(zz, v1, wp64[c1]);
            ffma2(rA, v0, wr64[2 * c0]);     ffma2(rA, v1, wr64[2 * c1]);
            ffma2(rB, v0, wr64[2 * c0 + 1]); ffma2(rB, v1, wr64[2 * c1 + 1]);
        }
        float z0, z1, r0, r1, r2, r3;
        unpk(zz, z0, z1);
        unpk(rA, r0, r1);
        unpk(rB, r2, r3);
        float score = 1.f / (1.f + expf(z0 - z1));

        int n = nbase + x;
        float fx = (float)x;
        float ulr = rintf((fy * 2.f + 1.f)  / scale);
        float ulc = rintf((fx * 2.f + 1.f)  / scale);
        float drr = rintf((fy * 2.f + 12.f) / scale);
        float drc = rintf((fx * 2.f + 12.f) / scale);

        float* pbx = out + (b * ntot + n) * 5;
        pbx[0] = ulr; pbx[1] = ulc; pbx[2] = drr; pbx[3] = drc; pbx[4] = score;

        float* prg = out + BATCH * ntot * 5 + (b * ntot + n) * 4;
        prg[0] = r0; prg[1] = r1; prg[2] = r2; prg[3] = r3;

        out[BATCH * ntot * 9 + b * ntot + n] = (score >= 0.6f) ? 1.f : 0.f;
    }
}

// ---------------------------------------------------------------------------
extern "C" void kernel_launch(void* const* d_in, const int* in_sizes, int n_in,
                              void* d_out, int out_size)
{
    const float* inp = (const float*)d_in[0];
    const float* w1  = (const float*)d_in[1];
    const float* b1  = (const float*)d_in[2];
    const float* w2  = (const float*)d_in[3];
    const float* b2  = (const float*)d_in[4];
    const float* w3  = (const float*)d_in[5];
    const float* b3  = (const float*)d_in[6];
    const float* wp  = (const float*)d_in[7];
    const float* bp  = (const float*)d_in[8];
    const float* wr  = (const float*)d_in[9];
    const float* br  = (const float*)d_in[10];
    float* out = (float*)d_out;
    (void)in_sizes; (void)n_in; (void)out_size;

    Meta m;
    int ns = 0;
    {
        double s = 12.0 / 20.0, mm = s * 1080.0;
        while (mm >= 12.0 && ns < NS) {
            m.hs[ns]   = (int)ceil(1080.0 * s);
            m.inv[ns]  = (float)(1080.0 / (double)m.hs[ns]);
            m.rinv[ns] = (float)((double)m.hs[ns] / 1080.0);
            m.scl[ns]  = (float)s;
            ns++;
            s *= 0.709; mm *= 0.709;
        }
    }

    int oT = 0, oI = 0, oP = 0, oC = 0, oW = 0, ntot = 0;
    m.bsRV[0] = m.bsCP[0] = m.bsC2[0] = m.bsC3[0] = 0;
    for (int k = 0; k < ns; k++) {
        int hs = m.hs[k], ws = hs;
        int h1 = hs - 2;
        int h2 = (h1 + 1) / 2, w2d = h2;
        int h3 = h2 - 2, w3d = h3;
        int h4 = h3 - 2, w4 = h4;
        int ph = (hs + 1) / 2;

        int wsP = (ws + 1) & ~1;            // even padded img row stride
        int w2p = (w2d + 11) & ~3;          // padded p1 row stride
        int w3p = (w3d + 11) & ~3;          // padded c2 row stride
        m.wsP[k] = wsP;
        m.w2p[k] = w2p;
        m.w3p[k] = w3p;

        m.offT[k] = oT;  oT += BATCH * HIN * ws * 3;
        m.offI[k] = oI;  oI += BATCH * hs * wsP * 3;
        m.offP[k] = oP;  oP += BATCH * h2 * w2p * 10;
        m.offC[k] = oC;  oC += BATCH * h3 * w3p * 16;
        m.offW[k] = oW;  oW += ws;
        m.noff[k] = ntot; ntot += h4 * w4;

        int T;
        T = BATCH * ph * ws;                   m.bsRV[k+1] = m.bsRV[k] + (T + 255) / 256;
        T = BATCH * h2 * w2d;                  m.bsCP[k+1] = m.bsCP[k] + (T + 127) / 128;
        T = BATCH * h3 * ((w3d + 3) / 4);      m.bsC2[k+1] = m.bsC2[k] + (T + 127) / 128;
        T = BATCH * h4 * ((w4 + 1) / 2);       m.bsC3[k+1] = m.bsC3[k] + (T + 127) / 128;
    }
    m.ntot = ntot;
    m.wsum = oW;
    for (int k = ns; k < NS; k++) {
        m.hs[k] = m.hs[ns-1]; m.inv[k] = m.inv[ns-1];
        m.rinv[k] = m.rinv[ns-1]; m.scl[k] = m.scl[ns-1];
        m.offT[k] = m.offI[k] = m.offP[k] = m.offC[k] = 0; m.noff[k] = 0;
        m.wsP[k] = 16; m.w2p[k] = 16; m.w3p[k] = 16;
        m.bsRV[k+1] = m.bsRV[k];
        m.bsCP[k+1] = m.bsCP[k]; m.bsC2[k+1] = m.bsC2[k]; m.bsC3[k+1] = m.bsC3[k];
        m.offW[k] = 0x7fffffff;
        m.bsRV[k] = 0x7fffffff; m.bsCP[k] = 0x7fffffff;
        m.bsC2[k] = 0x7fffffff; m.bsC3[k] = 0x7fffffff;
    }

    k_resize_h <<<BATCH * HIN, 256>>>(inp, m);
    k_resize_v <<<m.bsRV[ns], 256>>>(m);
    k_conv1pool<<<m.bsCP[ns], 128>>>(w1, b1, m);
    k_conv2    <<<m.bsC2[ns], 128>>>(w2, b2, m);
    k_conv3head<<<m.bsC3[ns], 128>>>(w3, b3, wp, bp, wr, br, out, m);
}